// round 10
// baseline (speedup 1.0000x reference)
#include <cuda_runtime.h>
#include <math.h>
#include <stdint.h>

// Problem-fixed sizes (dataset is fixed: N=100000, E=1600000, EL=1000000)
#define NMAX 100000
#define EMAX 1600000

// Scratch (device globals: allocation-free rule)
__device__ float g_dinv [NMAX];
__device__ int   g_cnt  [NMAX];      // in-edge count per col (no self loop)
__device__ int   g_start[NMAX];      // CSR exclusive start
__device__ int   g_cur  [NMAX];      // fill cursor (initialized to start)
__device__ int   g_bsum [128];       // scan block sums (98 used)
__device__ int   g_elist[EMAX];      // CSR edge list: row indices grouped by col
__device__ float g_h    [NMAX * 64];
__device__ float g_hw   [NMAX * 64]; // dinv[n] * (h @ W1)
__device__ float g_hw2  [NMAX * 32]; // dinv[n] * (out1 @ W2)
__device__ float g_z    [NMAX * 32];

// ---------------------------------------------------------------- f32x2 helpers (FFMA2: 2x fp32 FMA throughput; exact FFMA rounding)
__device__ __forceinline__ unsigned long long pk2(float lo, float hi) {
    unsigned long long d;
    asm("mov.b64 %0, {%1,%2};" : "=l"(d) : "f"(lo), "f"(hi));
    return d;
}
__device__ __forceinline__ void fma2(unsigned long long& d, unsigned long long a, unsigned long long b) {
    asm("fma.rn.f32x2 %0, %1, %2, %3;" : "=l"(d) : "l"(a), "l"(b), "l"(d));
}
__device__ __forceinline__ void upk2(unsigned long long v, float& lo, float& hi) {
    asm("mov.b64 {%0,%1}, %2;" : "=f"(lo), "=f"(hi) : "l"(v));
}

// fast tanh via EX2 (+clamp): ~2 ulp, vastly cheaper than libm tanhf
__device__ __forceinline__ float ftanh(float x) {
    float t = __expf(2.f * fminf(fmaxf(x, -15.f), 15.f));
    return __fdividef(t - 1.f, t + 1.f);
}
__device__ __forceinline__ float fsig(float x) {
    return __fdividef(1.f, 1.f + __expf(-x));
}

// ---------------------------------------------------------------- CSR build (5 launches)
__global__ void k_zero(int n) {
    int i = blockIdx.x * blockDim.x + threadIdx.x;
    if (i < n) g_cnt[i] = 0;
}

__global__ void k_hist(const int* __restrict__ ei, int E) {
    int e = blockIdx.x * blockDim.x + threadIdx.x;
    if (e < E) atomicAdd(&g_cnt[ei[E + e]], 1);   // col = ei[1][e]
}

// scan over g_cnt -> g_start (intra-block exclusive) + block totals + dinv.
__global__ void k_scan1(int n) {
    __shared__ int wsum[8];
    int tid = threadIdx.x;
    int base = blockIdx.x * 1024 + tid * 4;
    int v0 = (base     < n) ? g_cnt[base]     : 0;
    int v1 = (base + 1 < n) ? g_cnt[base + 1] : 0;
    int v2 = (base + 2 < n) ? g_cnt[base + 2] : 0;
    int v3 = (base + 3 < n) ? g_cnt[base + 3] : 0;
    if (base     < n) g_dinv[base]     = rsqrtf((float)(v0 + 1));
    if (base + 1 < n) g_dinv[base + 1] = rsqrtf((float)(v1 + 1));
    if (base + 2 < n) g_dinv[base + 2] = rsqrtf((float)(v2 + 1));
    if (base + 3 < n) g_dinv[base + 3] = rsqrtf((float)(v3 + 1));
    int t = v0 + v1 + v2 + v3;
    int lane = tid & 31, wid = tid >> 5;
    int s = t;
    #pragma unroll
    for (int o = 1; o < 32; o <<= 1) {
        int u = __shfl_up_sync(0xffffffffu, s, o);
        if (lane >= o) s += u;
    }
    if (lane == 31) wsum[wid] = s;
    __syncthreads();
    if (tid == 0) {
        int acc = 0;
        for (int w = 0; w < 8; w++) { int x = wsum[w]; wsum[w] = acc; acc += x; }
        g_bsum[blockIdx.x] = acc;
    }
    __syncthreads();
    int excl = s - t + wsum[wid];
    if (base     < n) g_start[base]     = excl;
    if (base + 1 < n) g_start[base + 1] = excl + v0;
    if (base + 2 < n) g_start[base + 2] = excl + v0 + v1;
    if (base + 3 < n) g_start[base + 3] = excl + v0 + v1 + v2;
}

__global__ void k_scan3(int n) {
    __shared__ int sp[8];
    int tid = threadIdx.x;
    int seg = (int)(blockIdx.x >> 2);
    int p = (tid < 128 && tid < seg) ? g_bsum[tid] : 0;
    #pragma unroll
    for (int o = 16; o > 0; o >>= 1) p += __shfl_down_sync(0xffffffffu, p, o);
    if ((tid & 31) == 0) sp[tid >> 5] = p;
    __syncthreads();
    if (tid == 0) sp[0] = sp[0] + sp[1] + sp[2] + sp[3];
    __syncthreads();
    int prefix = sp[0];
    int i = blockIdx.x * 256 + tid;
    if (i < n) {
        int st = g_start[i] + prefix;
        g_start[i] = st;
        g_cur[i]   = st;
    }
}

__global__ void k_fill(const int* __restrict__ ei, int E) {
    int e = blockIdx.x * blockDim.x + threadIdx.x;
    if (e >= E) return;
    int row = ei[e];
    int col = ei[E + e];
    int pos = atomicAdd(&g_cur[col], 1);
    g_elist[pos] = row;
}

// ---------------------------------------------------------------- LSTM (gates i,g,o; f gate dead since c0=0)
// FFMA2 node-pair packing: 8 nodes = 4 f32x2 accumulator pairs per gate.
#define LSTM_WS 192

__global__ void k_lstm(const float* __restrict__ x,
                       const float* __restrict__ Wih,
                       const float* __restrict__ bih,
                       const float* __restrict__ bhh,
                       int N) {
    extern __shared__ float smem[];
    float* sW = smem;                    // [64][192]: sW[k*192 + gi*64 + j]
    float* sb = sW + 64 * LSTM_WS;       // [192]
    float* sx = sb + 192;                // [32][64]
    int tid = threadIdx.x;

    for (int idx = tid; idx < 64 * 192; idx += 256) {
        int k  = idx & 63;
        int gj = idx >> 6;
        int gi = gj >> 6, j = gj & 63;
        int rb = (gi == 0) ? 0 : ((gi == 1) ? 128 : 192);
        sW[k * LSTM_WS + gj] = Wih[(rb + j) * 64 + k];
    }
    for (int idx = tid; idx < 192; idx += 256) {
        int gi = idx >> 6, j = idx & 63;
        int rb = (gi == 0) ? 0 : ((gi == 1) ? 128 : 192);
        sb[idx] = bih[rb + j] + bhh[rb + j];
    }
    __syncthreads();

    int j = tid & 63, slot = tid >> 6;   // 4 slots x 8 nodes = 32 nodes / iteration
    for (int base = blockIdx.x * 32; base < N; base += gridDim.x * 32) {
        __syncthreads();
        for (int idx = tid; idx < 2048; idx += 256) {
            int n = base + (idx >> 6);
            sx[idx] = (n < N) ? x[(size_t)n * 64 + (idx & 63)] : 0.f;
        }
        __syncthreads();

        float bi = sb[j], bg = sb[64 + j], bo = sb[128 + j];
        unsigned long long AI[4], AG[4], AO[4];
        #pragma unroll
        for (int p = 0; p < 4; p++) { AI[p] = pk2(bi, bi); AG[p] = pk2(bg, bg); AO[p] = pk2(bo, bo); }
        const float* xs = &sx[slot * 512];

        #pragma unroll
        for (int k = 0; k < 64; k += 4) {
            float4 xv[8];
            #pragma unroll
            for (int r = 0; r < 8; r++) xv[r] = *(const float4*)&xs[r * 64 + k];
            #pragma unroll
            for (int kk = 0; kk < 4; kk++) {
                float wi = sW[(k + kk) * LSTM_WS + j];
                float wg = sW[(k + kk) * LSTM_WS + 64 + j];
                float wo = sW[(k + kk) * LSTM_WS + 128 + j];
                unsigned long long wi2 = pk2(wi, wi), wg2 = pk2(wg, wg), wo2 = pk2(wo, wo);
                #pragma unroll
                for (int p = 0; p < 4; p++) {
                    unsigned long long vp = pk2((&xv[2 * p].x)[kk], (&xv[2 * p + 1].x)[kk]);
                    fma2(AI[p], vp, wi2);
                    fma2(AG[p], vp, wg2);
                    fma2(AO[p], vp, wo2);
                }
            }
        }

        int n0 = base + slot * 8;
        #pragma unroll
        for (int p = 0; p < 4; p++) {
            float i0, i1, gg0, gg1, o0, o1;
            upk2(AI[p], i0, i1);
            upk2(AG[p], gg0, gg1);
            upk2(AO[p], o0, o1);
            int na = n0 + 2 * p, nb2 = na + 1;
            if (na < N) {
                float c = fsig(i0) * ftanh(gg0);
                g_h[(size_t)na * 64 + j] = fsig(o0) * ftanh(c);
            }
            if (nb2 < N) {
                float c = fsig(i1) * ftanh(gg1);
                g_h[(size_t)nb2 * 64 + j] = fsig(o1) * ftanh(c);
            }
        }
    }
}

// ---------------------------------------------------------------- conv1 GEMM: g_hw = dinv[n] * (h @ W1)
// 32 j-threads x 2 cols (j, j+32) x 8 slots x 8 nodes = 64 nodes / iter, FFMA2 node-pairs.
__global__ void k_gemm1(const float* __restrict__ W1, int N) {
    __shared__ float sW[64 * 64];
    __shared__ float sx[64 * 64];
    int tid = threadIdx.x;
    for (int idx = tid; idx < 4096; idx += 256) sW[idx] = W1[idx];
    __syncthreads();

    int jj = tid & 31, slot = tid >> 5;
    for (int base = blockIdx.x * 64; base < N; base += gridDim.x * 64) {
        __syncthreads();
        for (int idx = tid; idx < 4096; idx += 256) {
            int n = base + (idx >> 6);
            sx[idx] = (n < N) ? g_h[(size_t)n * 64 + (idx & 63)] : 0.f;
        }
        __syncthreads();
        unsigned long long A0[4], A1[4];
        #pragma unroll
        for (int p = 0; p < 4; p++) { A0[p] = 0ull; A1[p] = 0ull; }
        const float* xs = &sx[slot * 512];
        #pragma unroll
        for (int k = 0; k < 64; k += 4) {
            float4 xv[8];
            #pragma unroll
            for (int r = 0; r < 8; r++) xv[r] = *(const float4*)&xs[r * 64 + k];
            #pragma unroll
            for (int kk = 0; kk < 4; kk++) {
                float w0 = sW[(k + kk) * 64 + jj];
                float w1 = sW[(k + kk) * 64 + jj + 32];
                unsigned long long wd0 = pk2(w0, w0), wd1 = pk2(w1, w1);
                #pragma unroll
                for (int p = 0; p < 4; p++) {
                    unsigned long long vp = pk2((&xv[2 * p].x)[kk], (&xv[2 * p + 1].x)[kk]);
                    fma2(A0[p], vp, wd0);
                    fma2(A1[p], vp, wd1);
                }
            }
        }
        int n0 = base + slot * 8;
        #pragma unroll
        for (int p = 0; p < 4; p++) {
            float a00, a01, a10, a11;
            upk2(A0[p], a00, a01);
            upk2(A1[p], a10, a11);
            int na = n0 + 2 * p, nb2 = na + 1;
            if (na < N) {
                float d = g_dinv[na];
                g_hw[(size_t)na * 64 + jj]      = a00 * d;
                g_hw[(size_t)na * 64 + jj + 32] = a10 * d;
            }
            if (nb2 < N) {
                float d = g_dinv[nb2];
                g_hw[(size_t)nb2 * 64 + jj]      = a01 * d;
                g_hw[(size_t)nb2 * 64 + jj + 32] = a11 * d;
            }
        }
    }
}

// ---------------------------------------------------------------- fused conv1-gather + conv2 GEMM
// Phase A: gather out1 tile (64 cols) into smem: out1 = relu(dinv[c]*(hws[c]+sum)+b1)
// Phase B: g_hw2 = dinv[n] * (out1 @ W2)  (FFMA2 node-pairs)
__global__ void k_conv2a(const float* __restrict__ W2, const float* __restrict__ b1, int N) {
    __shared__ float sW[64 * 32];
    __shared__ float sx[64 * 64];
    int tid = threadIdx.x;
    for (int idx = tid; idx < 2048; idx += 256) sW[idx] = W2[idx];

    int base = blockIdx.x * 64;

    // Phase A: 64 cols x 16 lanes = 1024 units, 4 per thread
    int ln = tid & 15;
    float4 bv = *(const float4*)&b1[ln * 4];
    #pragma unroll
    for (int rep = 0; rep < 4; rep++) {
        int cl = (tid >> 4) + rep * 16;      // 0..63
        int c = base + cl;
        float4 o = make_float4(0.f, 0.f, 0.f, 0.f);
        if (c < N) {
            int s = g_start[c], cnt = g_cnt[c];
            float4 acc = *(const float4*)&g_hw[(size_t)c * 64 + ln * 4];   // self term
            int r = (cnt > 0) ? __ldg(&g_elist[s]) : 0;
            for (int i = 0; i < cnt; i++) {
                int rn = (i + 1 < cnt) ? __ldg(&g_elist[s + i + 1]) : 0;
                float4 v = *(const float4*)&g_hw[(size_t)r * 64 + ln * 4];
                acc.x += v.x; acc.y += v.y; acc.z += v.z; acc.w += v.w;
                r = rn;
            }
            float dc = g_dinv[c];
            o.x = fmaxf(acc.x * dc + bv.x, 0.f);
            o.y = fmaxf(acc.y * dc + bv.y, 0.f);
            o.z = fmaxf(acc.z * dc + bv.z, 0.f);
            o.w = fmaxf(acc.w * dc + bv.w, 0.f);
        }
        *(float4*)&sx[cl * 64 + ln * 4] = o;
    }
    __syncthreads();

    // Phase B: GEMM, 8 slots x 8 nodes, FFMA2
    int j = tid & 31, slot = tid >> 5;
    unsigned long long A[4];
    #pragma unroll
    for (int p = 0; p < 4; p++) A[p] = 0ull;
    const float* xs = &sx[slot * 512];
    #pragma unroll
    for (int k = 0; k < 64; k += 4) {
        float4 xv[8];
        #pragma unroll
        for (int r = 0; r < 8; r++) xv[r] = *(const float4*)&xs[r * 64 + k];
        #pragma unroll
        for (int kk = 0; kk < 4; kk++) {
            float w = sW[(k + kk) * 32 + j];
            unsigned long long wd = pk2(w, w);
            #pragma unroll
            for (int p = 0; p < 4; p++) {
                unsigned long long vp = pk2((&xv[2 * p].x)[kk], (&xv[2 * p + 1].x)[kk]);
                fma2(A[p], vp, wd);
            }
        }
    }
    int n0 = base + slot * 8;
    #pragma unroll
    for (int p = 0; p < 4; p++) {
        float a0, a1;
        upk2(A[p], a0, a1);
        int na = n0 + 2 * p, nb2 = na + 1;
        if (na < N)  g_hw2[(size_t)na * 32 + j]  = a0 * g_dinv[na];
        if (nb2 < N) g_hw2[(size_t)nb2 * 32 + j] = a1 * g_dinv[nb2];
    }
}

// ---------------------------------------------------------------- conv2 gather: z[c] = dinv[c]*(hw2s[c] + sum) + b2
__global__ void k_gather2(const float* __restrict__ b2, int N) {
    int g = blockIdx.x * blockDim.x + threadIdx.x;
    int c = g >> 3, ln = g & 7;
    if (c >= N) return;
    int s = g_start[c], cnt = g_cnt[c];
    float4 acc = *(const float4*)&g_hw2[(size_t)c * 32 + ln * 4];  // self term
    int r = (cnt > 0) ? __ldg(&g_elist[s]) : 0;
    for (int i = 0; i < cnt; i++) {
        int rn = (i + 1 < cnt) ? __ldg(&g_elist[s + i + 1]) : 0;
        float4 v = *(const float4*)&g_hw2[(size_t)r * 32 + ln * 4];
        acc.x += v.x; acc.y += v.y; acc.z += v.z; acc.w += v.w;
        r = rn;
    }
    float dc = g_dinv[c];
    float4 b = *(const float4*)&b2[ln * 4];
    float4 o;
    o.x = acc.x * dc + b.x;
    o.y = acc.y * dc + b.y;
    o.z = acc.z * dc + b.z;
    o.w = acc.w * dc + b.w;
    *(float4*)&g_z[(size_t)c * 32 + ln * 4] = o;
}

// ---------------------------------------------------------------- label-edge dot (8 threads/edge)
__global__ void k_dot(const int* __restrict__ eli, float* __restrict__ out, int EL) {
    int t = blockIdx.x * blockDim.x + threadIdx.x;
    int e = t >> 3, c = t & 7;
    if (e >= EL) return;
    int s = __ldg(&eli[e]);
    int d = __ldg(&eli[EL + e]);
    float4 a = *(const float4*)&g_z[(size_t)s * 32 + c * 4];
    float4 b = *(const float4*)&g_z[(size_t)d * 32 + c * 4];
    float p = a.x * b.x + a.y * b.y + a.z * b.z + a.w * b.w;
    p += __shfl_down_sync(0xffffffffu, p, 4, 8);
    p += __shfl_down_sync(0xffffffffu, p, 2, 8);
    p += __shfl_down_sync(0xffffffffu, p, 1, 8);
    if (c == 0) out[e] = p;
}

// ---------------------------------------------------------------- launch
extern "C" void kernel_launch(void* const* d_in, const int* in_sizes, int n_in,
                              void* d_out, int out_size) {
    const float* x   = (const float*)d_in[0];
    const int*   ei  = (const int*)  d_in[1];
    const int*   eli = (const int*)  d_in[2];
    const float* Wih = (const float*)d_in[3];
    // d_in[4] = W_hh: unused (h0 == 0 => W_hh @ h0 == 0)
    const float* bih = (const float*)d_in[5];
    const float* bhh = (const float*)d_in[6];
    const float* W1  = (const float*)d_in[7];
    const float* b1  = (const float*)d_in[8];
    const float* W2  = (const float*)d_in[9];
    const float* b2  = (const float*)d_in[10];
    float* out = (float*)d_out;

    int N  = in_sizes[0] / 64;
    int E  = in_sizes[1] / 2;
    int EL = in_sizes[2] / 2;

    const int LSTM_SMEM = (64 * LSTM_WS + 192 + 2048) * 4;  // 58112 B
    cudaFuncSetAttribute(k_lstm, cudaFuncAttributeMaxDynamicSharedMemorySize, LSTM_SMEM);
    (void)cudaGetLastError();  // never poison the capture stream

    int nb    = (N + 255) / 256;
    int nscan = (N + 1023) / 1024;

    // CSR build + norms (5 launches)
    k_zero <<<nb, 256>>>(N);
    k_hist <<<(E + 255) / 256, 256>>>(ei, E);
    k_scan1<<<nscan, 256>>>(N);
    k_scan3<<<nb, 256>>>(N);
    k_fill <<<(E + 255) / 256, 256>>>(ei, E);

    // Pipeline
    k_lstm   <<<444, 256, LSTM_SMEM>>>(x, Wih, bih, bhh, N);
    k_gemm1  <<<592, 256>>>(W1, N);
    k_conv2a <<<(N + 63) / 64, 256>>>(W2, b1, N);
    k_gather2<<<(N * 8 + 255) / 256, 256>>>(b2, N);
    k_dot    <<<(EL * 8 + 255) / 256, 256>>>(eli, out, EL);
}

// round 11
// speedup vs baseline: 1.1297x; 1.1297x over previous
#include <cuda_runtime.h>
#include <math.h>
#include <stdint.h>

// Problem-fixed sizes (dataset is fixed: N=100000, E=1600000, EL=1000000)
#define NMAX 100000
#define EMAX 1600000

typedef unsigned long long ull;

// Scratch (device globals: allocation-free rule)
__device__ float g_dinv [NMAX];
__device__ int   g_cnt  [NMAX];
__device__ int   g_start[NMAX];
__device__ int   g_cur  [NMAX];
__device__ int   g_bsum [128];
__device__ int   g_elist[EMAX];
__device__ float g_hw   [NMAX * 64]; // dinv[n] * (h @ W1)
__device__ float g_hw2  [NMAX * 32]; // dinv[n] * (out1 @ W2)
__device__ float g_z    [NMAX * 32];

// ---------------------------------------------------------------- f32x2 helpers
__device__ __forceinline__ ull pk2(float lo, float hi) {
    ull d; asm("mov.b64 %0, {%1,%2};" : "=l"(d) : "f"(lo), "f"(hi)); return d;
}
__device__ __forceinline__ void fma2(ull& d, ull a, ull b) {
    asm("fma.rn.f32x2 %0, %1, %2, %3;" : "=l"(d) : "l"(a), "l"(b), "l"(d));
}
__device__ __forceinline__ void upk2(ull v, float& lo, float& hi) {
    asm("mov.b64 {%0,%1}, %2;" : "=f"(lo), "=f"(hi) : "l"(v));
}
__device__ __forceinline__ ull lds64(const float2* p) {
    return *reinterpret_cast<const ull*>(p);
}

// fast tanh/sigmoid via EX2 (+clamp): ~2 ulp
__device__ __forceinline__ float ftanh(float x) {
    float t = __expf(2.f * fminf(fmaxf(x, -15.f), 15.f));
    return __fdividef(t - 1.f, t + 1.f);
}
__device__ __forceinline__ float fsig(float x) {
    return __fdividef(1.f, 1.f + __expf(-x));
}

// ---------------------------------------------------------------- CSR build (5 launches)
__global__ void k_zero(int n) {
    int i = blockIdx.x * blockDim.x + threadIdx.x;
    if (i < n) g_cnt[i] = 0;
}

__global__ void k_hist(const int* __restrict__ ei, int E) {
    int e = blockIdx.x * blockDim.x + threadIdx.x;
    if (e < E) atomicAdd(&g_cnt[ei[E + e]], 1);
}

__global__ void k_scan1(int n) {
    __shared__ int wsum[8];
    int tid = threadIdx.x;
    int base = blockIdx.x * 1024 + tid * 4;
    int v0 = (base     < n) ? g_cnt[base]     : 0;
    int v1 = (base + 1 < n) ? g_cnt[base + 1] : 0;
    int v2 = (base + 2 < n) ? g_cnt[base + 2] : 0;
    int v3 = (base + 3 < n) ? g_cnt[base + 3] : 0;
    if (base     < n) g_dinv[base]     = rsqrtf((float)(v0 + 1));
    if (base + 1 < n) g_dinv[base + 1] = rsqrtf((float)(v1 + 1));
    if (base + 2 < n) g_dinv[base + 2] = rsqrtf((float)(v2 + 1));
    if (base + 3 < n) g_dinv[base + 3] = rsqrtf((float)(v3 + 1));
    int t = v0 + v1 + v2 + v3;
    int lane = tid & 31, wid = tid >> 5;
    int s = t;
    #pragma unroll
    for (int o = 1; o < 32; o <<= 1) {
        int u = __shfl_up_sync(0xffffffffu, s, o);
        if (lane >= o) s += u;
    }
    if (lane == 31) wsum[wid] = s;
    __syncthreads();
    if (tid == 0) {
        int acc = 0;
        for (int w = 0; w < 8; w++) { int x = wsum[w]; wsum[w] = acc; acc += x; }
        g_bsum[blockIdx.x] = acc;
    }
    __syncthreads();
    int excl = s - t + wsum[wid];
    if (base     < n) g_start[base]     = excl;
    if (base + 1 < n) g_start[base + 1] = excl + v0;
    if (base + 2 < n) g_start[base + 2] = excl + v0 + v1;
    if (base + 3 < n) g_start[base + 3] = excl + v0 + v1 + v2;
}

__global__ void k_scan3(int n) {
    __shared__ int sp[8];
    int tid = threadIdx.x;
    int seg = (int)(blockIdx.x >> 2);
    int p = (tid < 128 && tid < seg) ? g_bsum[tid] : 0;
    #pragma unroll
    for (int o = 16; o > 0; o >>= 1) p += __shfl_down_sync(0xffffffffu, p, o);
    if ((tid & 31) == 0) sp[tid >> 5] = p;
    __syncthreads();
    if (tid == 0) sp[0] = sp[0] + sp[1] + sp[2] + sp[3];
    __syncthreads();
    int prefix = sp[0];
    int i = blockIdx.x * 256 + tid;
    if (i < n) {
        int st = g_start[i] + prefix;
        g_start[i] = st;
        g_cur[i]   = st;
    }
}

__global__ void k_fill(const int* __restrict__ ei, int E) {
    int e = blockIdx.x * blockDim.x + threadIdx.x;
    if (e >= E) return;
    int row = ei[e];
    int col = ei[E + e];
    int pos = atomicAdd(&g_cur[col], 1);
    g_elist[pos] = row;
}

// ---------------------------------------------------------------- fused LSTM + conv1 GEMM
// Phase 1: gates (i,g,o only; f dead since c0=0) via col-pair FFMA2 (interleaved weight pairs).
// Phase 2: h (written to smem) @ W1, scaled by dinv -> g_hw.  g_h round-trip eliminated.
// smem: sWp float2[64*96] (49152B) | sW1p float2[64*32] (16384B) | sb f[192] | sx f[32*64]
#define SM_WP   0
#define SM_W1P  (64 * 96)            // in float2 units
#define SM_B    ((64 * 96 + 64 * 32) * 2)   // in float units
#define SM_X    (SM_B + 192)
#define LSTM_SMEM_BYTES ((64 * 96 + 64 * 32) * 8 + (192 + 2048) * 4)  // 74496

__global__ void __launch_bounds__(256, 3)
k_lstm_fused(const float* __restrict__ x,
             const float* __restrict__ Wih,
             const float* __restrict__ bih,
             const float* __restrict__ bhh,
             const float* __restrict__ W1,
             int N) {
    extern __shared__ float smem[];
    float2* sWp  = reinterpret_cast<float2*>(smem);            // [k][gi*32+jj] pair (j, j+32)
    float2* sW1p = reinterpret_cast<float2*>(smem) + SM_W1P;   // [k][jj] pair (j, j+32)
    float*  sb   = smem + SM_B;                                // [gi*64 + j]
    float*  sx   = smem + SM_X;                                // [32][64]
    int tid = threadIdx.x;

    // Stage gate weights as interleaved col-pairs: sWp[k*96+gi*32+jj] = {Wih[(rb+jj)k], Wih[(rb+jj+32)k]}
    for (int idx = tid; idx < 64 * 96; idx += 256) {
        int k = idx / 96, gj = idx - k * 96;
        int gi = gj >> 5, jj = gj & 31;
        int rb = (gi == 0) ? 0 : ((gi == 1) ? 128 : 192);
        sWp[idx] = make_float2(Wih[(rb + jj) * 64 + k], Wih[(rb + jj + 32) * 64 + k]);
    }
    // Stage W1 pairs: sW1p[k*32+jj] = {W1[k*64+jj], W1[k*64+jj+32]}
    for (int idx = tid; idx < 64 * 32; idx += 256) {
        int k = idx >> 5, jj = idx & 31;
        sW1p[idx] = make_float2(W1[k * 64 + jj], W1[k * 64 + jj + 32]);
    }
    for (int idx = tid; idx < 192; idx += 256) {
        int gi = idx >> 6, j = idx & 63;
        int rb = (gi == 0) ? 0 : ((gi == 1) ? 128 : 192);
        sb[idx] = bih[rb + j] + bhh[rb + j];
    }
    __syncthreads();

    int jj = tid & 31, slot = tid >> 5;   // 8 slots x 4 nodes = 32 nodes / iteration
    ull bi2 = pk2(sb[jj], sb[jj + 32]);
    ull bg2 = pk2(sb[64 + jj], sb[64 + jj + 32]);
    ull bo2 = pk2(sb[128 + jj], sb[128 + jj + 32]);

    for (int base = blockIdx.x * 32; base < N; base += gridDim.x * 32) {
        __syncthreads();
        for (int idx = tid; idx < 2048; idx += 256) {
            int n = base + (idx >> 6);
            sx[idx] = (n < N) ? x[(size_t)n * 64 + (idx & 63)] : 0.f;
        }
        __syncthreads();

        // ---- Phase 1: gates GEMM (col-pair FFMA2) ----
        ull AI[4], AG[4], AO[4];
        #pragma unroll
        for (int r = 0; r < 4; r++) { AI[r] = bi2; AG[r] = bg2; AO[r] = bo2; }
        const float* xs = &sx[slot * 256];

        #pragma unroll
        for (int k = 0; k < 64; k += 4) {
            float4 xv[4];
            #pragma unroll
            for (int r = 0; r < 4; r++) xv[r] = *(const float4*)&xs[r * 64 + k];
            #pragma unroll
            for (int kk = 0; kk < 4; kk++) {
                const float2* wrow = &sWp[(k + kk) * 96];
                ull wi2 = lds64(&wrow[jj]);
                ull wg2 = lds64(&wrow[32 + jj]);
                ull wo2 = lds64(&wrow[64 + jj]);
                #pragma unroll
                for (int r = 0; r < 4; r++) {
                    float v = (&xv[r].x)[kk];
                    ull vp = pk2(v, v);
                    fma2(AI[r], vp, wi2);
                    fma2(AG[r], vp, wg2);
                    fma2(AO[r], vp, wo2);
                }
            }
        }

        // ---- activations; write h into sx (x fully consumed) ----
        float hlo[4], hhi[4];
        #pragma unroll
        for (int r = 0; r < 4; r++) {
            float il, ih, gl, gh, ol, oh;
            upk2(AI[r], il, ih);
            upk2(AG[r], gl, gh);
            upk2(AO[r], ol, oh);
            float cl = fsig(il) * ftanh(gl);
            float ch = fsig(ih) * ftanh(gh);
            hlo[r] = fsig(ol) * ftanh(cl);
            hhi[r] = fsig(oh) * ftanh(ch);
        }
        __syncthreads();   // all phase-1 reads of sx complete
        #pragma unroll
        for (int r = 0; r < 4; r++) {
            int ln = slot * 4 + r;
            sx[ln * 64 + jj]      = hlo[r];
            sx[ln * 64 + jj + 32] = hhi[r];
        }
        __syncthreads();

        // ---- Phase 2: hw = dinv * (h @ W1), col-pair FFMA2 ----
        ull B[4];
        #pragma unroll
        for (int r = 0; r < 4; r++) B[r] = 0ull;
        #pragma unroll
        for (int k = 0; k < 64; k += 4) {
            float4 xv[4];
            #pragma unroll
            for (int r = 0; r < 4; r++) xv[r] = *(const float4*)&xs[r * 64 + k];
            #pragma unroll
            for (int kk = 0; kk < 4; kk++) {
                ull wd = lds64(&sW1p[(k + kk) * 32 + jj]);
                #pragma unroll
                for (int r = 0; r < 4; r++) {
                    float v = (&xv[r].x)[kk];
                    ull vp = pk2(v, v);
                    fma2(B[r], vp, wd);
                }
            }
        }
        #pragma unroll
        for (int r = 0; r < 4; r++) {
            int n = base + slot * 4 + r;
            if (n < N) {
                float alo, ahi;
                upk2(B[r], alo, ahi);
                float d = g_dinv[n];
                g_hw[(size_t)n * 64 + jj]      = alo * d;
                g_hw[(size_t)n * 64 + jj + 32] = ahi * d;
            }
        }
    }
}

// ---------------------------------------------------------------- fused conv1-gather + conv2 GEMM
__global__ void k_conv2a(const float* __restrict__ W2, const float* __restrict__ b1, int N) {
    __shared__ float sW[64 * 32];
    __shared__ float sx[64 * 64];
    int tid = threadIdx.x;
    for (int idx = tid; idx < 2048; idx += 256) sW[idx] = W2[idx];

    int base = blockIdx.x * 64;

    int ln = tid & 15;
    float4 bv = *(const float4*)&b1[ln * 4];
    #pragma unroll
    for (int rep = 0; rep < 4; rep++) {
        int cl = (tid >> 4) + rep * 16;
        int c = base + cl;
        float4 o = make_float4(0.f, 0.f, 0.f, 0.f);
        if (c < N) {
            int s = g_start[c], cnt = g_cnt[c];
            float4 acc = *(const float4*)&g_hw[(size_t)c * 64 + ln * 4];
            int r = (cnt > 0) ? __ldg(&g_elist[s]) : 0;
            for (int i = 0; i < cnt; i++) {
                int rn = (i + 1 < cnt) ? __ldg(&g_elist[s + i + 1]) : 0;
                float4 v = *(const float4*)&g_hw[(size_t)r * 64 + ln * 4];
                acc.x += v.x; acc.y += v.y; acc.z += v.z; acc.w += v.w;
                r = rn;
            }
            float dc = g_dinv[c];
            o.x = fmaxf(acc.x * dc + bv.x, 0.f);
            o.y = fmaxf(acc.y * dc + bv.y, 0.f);
            o.z = fmaxf(acc.z * dc + bv.z, 0.f);
            o.w = fmaxf(acc.w * dc + bv.w, 0.f);
        }
        *(float4*)&sx[cl * 64 + ln * 4] = o;
    }
    __syncthreads();

    int j = tid & 31, slot = tid >> 5;
    ull A[4];
    #pragma unroll
    for (int p = 0; p < 4; p++) A[p] = 0ull;
    const float* xs = &sx[slot * 512];
    #pragma unroll
    for (int k = 0; k < 64; k += 4) {
        float4 xv[8];
        #pragma unroll
        for (int r = 0; r < 8; r++) xv[r] = *(const float4*)&xs[r * 64 + k];
        #pragma unroll
        for (int kk = 0; kk < 4; kk++) {
            float w = sW[(k + kk) * 32 + j];
            ull wd = pk2(w, w);
            #pragma unroll
            for (int p = 0; p < 4; p++) {
                ull vp = pk2((&xv[2 * p].x)[kk], (&xv[2 * p + 1].x)[kk]);
                fma2(A[p], vp, wd);
            }
        }
    }
    int n0 = base + slot * 8;
    #pragma unroll
    for (int p = 0; p < 4; p++) {
        float a0, a1;
        upk2(A[p], a0, a1);
        int na = n0 + 2 * p, nb2 = na + 1;
        if (na < N)  g_hw2[(size_t)na * 32 + j]  = a0 * g_dinv[na];
        if (nb2 < N) g_hw2[(size_t)nb2 * 32 + j] = a1 * g_dinv[nb2];
    }
}

// ---------------------------------------------------------------- conv2 gather
__global__ void k_gather2(const float* __restrict__ b2, int N) {
    int g = blockIdx.x * blockDim.x + threadIdx.x;
    int c = g >> 3, ln = g & 7;
    if (c >= N) return;
    int s = g_start[c], cnt = g_cnt[c];
    float4 acc = *(const float4*)&g_hw2[(size_t)c * 32 + ln * 4];
    int r = (cnt > 0) ? __ldg(&g_elist[s]) : 0;
    for (int i = 0; i < cnt; i++) {
        int rn = (i + 1 < cnt) ? __ldg(&g_elist[s + i + 1]) : 0;
        float4 v = *(const float4*)&g_hw2[(size_t)r * 32 + ln * 4];
        acc.x += v.x; acc.y += v.y; acc.z += v.z; acc.w += v.w;
        r = rn;
    }
    float dc = g_dinv[c];
    float4 b = *(const float4*)&b2[ln * 4];
    float4 o;
    o.x = acc.x * dc + b.x;
    o.y = acc.y * dc + b.y;
    o.z = acc.z * dc + b.z;
    o.w = acc.w * dc + b.w;
    *(float4*)&g_z[(size_t)c * 32 + ln * 4] = o;
}

// ---------------------------------------------------------------- label-edge dot
__global__ void k_dot(const int* __restrict__ eli, float* __restrict__ out, int EL) {
    int t = blockIdx.x * blockDim.x + threadIdx.x;
    int e = t >> 3, c = t & 7;
    if (e >= EL) return;
    int s = __ldg(&eli[e]);
    int d = __ldg(&eli[EL + e]);
    float4 a = *(const float4*)&g_z[(size_t)s * 32 + c * 4];
    float4 b = *(const float4*)&g_z[(size_t)d * 32 + c * 4];
    float p = a.x * b.x + a.y * b.y + a.z * b.z + a.w * b.w;
    p += __shfl_down_sync(0xffffffffu, p, 4, 8);
    p += __shfl_down_sync(0xffffffffu, p, 2, 8);
    p += __shfl_down_sync(0xffffffffu, p, 1, 8);
    if (c == 0) out[e] = p;
}

// ---------------------------------------------------------------- launch
extern "C" void kernel_launch(void* const* d_in, const int* in_sizes, int n_in,
                              void* d_out, int out_size) {
    const float* x   = (const float*)d_in[0];
    const int*   ei  = (const int*)  d_in[1];
    const int*   eli = (const int*)  d_in[2];
    const float* Wih = (const float*)d_in[3];
    // d_in[4] = W_hh: unused (h0 == 0 => W_hh @ h0 == 0)
    const float* bih = (const float*)d_in[5];
    const float* bhh = (const float*)d_in[6];
    const float* W1  = (const float*)d_in[7];
    const float* b1  = (const float*)d_in[8];
    const float* W2  = (const float*)d_in[9];
    const float* b2  = (const float*)d_in[10];
    float* out = (float*)d_out;

    int N  = in_sizes[0] / 64;
    int E  = in_sizes[1] / 2;
    int EL = in_sizes[2] / 2;

    cudaFuncSetAttribute(k_lstm_fused, cudaFuncAttributeMaxDynamicSharedMemorySize, LSTM_SMEM_BYTES);
    (void)cudaGetLastError();  // never poison the capture stream

    int nb    = (N + 255) / 256;
    int nscan = (N + 1023) / 1024;

    // CSR build + norms (5 launches)
    k_zero <<<nb, 256>>>(N);
    k_hist <<<(E + 255) / 256, 256>>>(ei, E);
    k_scan1<<<nscan, 256>>>(N);
    k_scan3<<<nb, 256>>>(N);
    k_fill <<<(E + 255) / 256, 256>>>(ei, E);

    // Pipeline
    k_lstm_fused<<<444, 256, LSTM_SMEM_BYTES>>>(x, Wih, bih, bhh, W1, N);
    k_conv2a    <<<(N + 63) / 64, 256>>>(W2, b1, N);
    k_gather2   <<<(N * 8 + 255) / 256, 256>>>(b2, N);
    k_dot       <<<(EL * 8 + 255) / 256, 256>>>(eli, out, EL);
}